// round 14
// baseline (speedup 1.0000x reference)
#include <cuda_runtime.h>
#include <cuda_bf16.h>
#include <cstdint>
#include <math.h>

#define DIM    1024
#define BATCH  2
#define TLEN   2048
#define HEADS  16
#define HD     64
#define ROWS   (BATCH*TLEN)
#define HROWS  (BATCH*HEADS*TLEN)
#define THRESH 0.29514f
#define SHARP  15.0f

__device__ float d_Q[HROWS*HD];
__device__ float d_K[HROWS*HD];
__device__ float d_V[HROWS*HD];
__device__ float d_gq[HROWS];
__device__ __align__(16) __nv_bfloat16 d_Qh[HROWS*HD];
__device__ __align__(16) __nv_bfloat16 d_Ql[HROWS*HD];
__device__ __align__(16) __nv_bfloat16 d_Kh[HROWS*HD];
__device__ __align__(16) __nv_bfloat16 d_Kl[HROWS*HD];
__device__ __align__(16) __nv_bfloat16 d_Vth[HROWS*HD];  // [b,h][d][s]
__device__ __align__(16) __nv_bfloat16 d_Vtl[HROWS*HD];
__device__ __align__(16) __nv_bfloat16 d_Wth[4][DIM*DIM];
__device__ __align__(16) __nv_bfloat16 d_Wtl[4][DIM*DIM];
__device__ __align__(16) __nv_bfloat16 d_Xnh[ROWS*DIM];
__device__ __align__(16) __nv_bfloat16 d_Xnl[ROWS*DIM];
__device__ __align__(16) __nv_bfloat16 d_Xh[ROWS*DIM];
__device__ __align__(16) __nv_bfloat16 d_Xl[ROWS*DIM];
__device__ __align__(16) __nv_bfloat16 d_Ch[ROWS*DIM];
__device__ __align__(16) __nv_bfloat16 d_Cl[ROWS*DIM];

// ---------------- mma.sync / helpers ----------------
__device__ __forceinline__ void mma_bf16(float* c, const uint32_t* a, const uint32_t* b) {
    asm volatile(
        "mma.sync.aligned.m16n8k16.row.col.f32.bf16.bf16.f32 "
        "{%0,%1,%2,%3}, {%4,%5,%6,%7}, {%8,%9}, {%0,%1,%2,%3};"
        : "+f"(c[0]), "+f"(c[1]), "+f"(c[2]), "+f"(c[3])
        : "r"(a[0]), "r"(a[1]), "r"(a[2]), "r"(a[3]), "r"(b[0]), "r"(b[1]));
}
__device__ __forceinline__ void ldsm4(uint32_t* r, uint32_t addr) {
    asm volatile("ldmatrix.sync.aligned.m8n8.x4.shared.b16 {%0,%1,%2,%3}, [%4];"
                 : "=r"(r[0]), "=r"(r[1]), "=r"(r[2]), "=r"(r[3]) : "r"(addr));
}
__device__ __forceinline__ uint32_t bfpack2(float a, float b) {
    __nv_bfloat162 p = __floats2bfloat162_rn(a, b);
    return *reinterpret_cast<uint32_t*>(&p);
}
__device__ __forceinline__ float bflo(float v) {
    return v - __bfloat162float(__float2bfloat16_rn(v));
}
__device__ __forceinline__ void bf_split(float v, __nv_bfloat16& h, __nv_bfloat16& l) {
    h = __float2bfloat16_rn(v);
    l = __float2bfloat16_rn(v - __bfloat162float(h));
}
__device__ __forceinline__ void cp16(uint32_t smem_addr, const void* gptr) {
    asm volatile("cp.async.cg.shared.global [%0], [%1], 16;"
                 :: "r"(smem_addr), "l"(gptr) : "memory");
}
#define CP_COMMIT() asm volatile("cp.async.commit_group;" ::: "memory")
#define CP_WAIT0()  asm volatile("cp.async.wait_group 0;" ::: "memory")

// ---------------- LayerNorm (+ bf16 hi/lo split of xnorm) --------------------
__global__ void ln_kernel(const float* __restrict__ x,
                          const float* __restrict__ w,
                          const float* __restrict__ bvec) {
    int row = blockIdx.x, tid = threadIdx.x;
    float4 v = ((const float4*)(x + (size_t)row*DIM))[tid];
    float s  = v.x+v.y+v.z+v.w;
    float ss = v.x*v.x+v.y*v.y+v.z*v.z+v.w*v.w;
    #pragma unroll
    for (int o = 16; o > 0; o >>= 1) {
        s  += __shfl_xor_sync(~0u, s, o);
        ss += __shfl_xor_sync(~0u, ss, o);
    }
    __shared__ float rs[8], rss[8];
    int wid = tid >> 5, lane = tid & 31;
    if (lane == 0) { rs[wid] = s; rss[wid] = ss; }
    __syncthreads();
    s = 0.f; ss = 0.f;
    #pragma unroll
    for (int i = 0; i < 8; i++) { s += rs[i]; ss += rss[i]; }
    float mean = s*(1.f/DIM), var = ss*(1.f/DIM) - mean*mean;
    float rstd = rsqrtf(var + 1e-5f);
    float4 wv = ((const float4*)w)[tid], bv = ((const float4*)bvec)[tid];
    float4 o;
    o.x = (v.x-mean)*rstd*wv.x + bv.x;  o.y = (v.y-mean)*rstd*wv.y + bv.y;
    o.z = (v.z-mean)*rstd*wv.z + bv.z;  o.w = (v.w-mean)*rstd*wv.w + bv.w;
    uint2 hw = make_uint2(bfpack2(o.x, o.y), bfpack2(o.z, o.w));
    uint2 lw = make_uint2(bfpack2(bflo(o.x), bflo(o.y)), bfpack2(bflo(o.z), bflo(o.w)));
    *(uint2*)&d_Xnh[(size_t)row*DIM + tid*4] = hw;
    *(uint2*)&d_Xnl[(size_t)row*DIM + tid*4] = lw;
}

// ---------------- split x into bf16 hi/lo ----------------
__global__ void split_x(const float* __restrict__ x) {
    int i = (blockIdx.x*256 + threadIdx.x)*4;
    float4 v = *(const float4*)(x + i);
    *(uint2*)&d_Xh[i] = make_uint2(bfpack2(v.x, v.y), bfpack2(v.z, v.w));
    *(uint2*)&d_Xl[i] = make_uint2(bfpack2(bflo(v.x), bflo(v.y)), bfpack2(bflo(v.z), bflo(v.w)));
}

// ---------------- weight transpose + split: Wt[z][n][k] ----------------------
__global__ void wsplit(const float* __restrict__ Wq, const float* __restrict__ Wk,
                       const float* __restrict__ Wv, const float* __restrict__ Wo) {
    __shared__ float tile[32][33];
    int z = blockIdx.z;
    const float* W = (z==0) ? Wq : (z==1) ? Wk : (z==2) ? Wv : Wo;
    int n0 = blockIdx.x*32, k0 = blockIdx.y*32;
    int tx = threadIdx.x, ty = threadIdx.y;
    #pragma unroll
    for (int i = 0; i < 4; i++)
        tile[ty+8*i][tx] = W[(size_t)(k0+ty+8*i)*DIM + n0 + tx];
    __syncthreads();
    #pragma unroll
    for (int i = 0; i < 4; i++) {
        float v = tile[tx][ty+8*i];
        __nv_bfloat16 h, l;
        bf_split(v, h, l);
        d_Wth[z][(size_t)(n0+ty+8*i)*DIM + k0 + tx] = h;
        d_Wtl[z][(size_t)(n0+ty+8*i)*DIM + k0 + tx] = l;
    }
}

// -------- bf16x3 GEMM: pre-split, cp.async 2-stage, ldmatrix, 1 sync/chunk ---
#define GT_ST 20
#define TILEW (128*GT_ST)
#define SSTAGE (4*TILEW)
#define GEMM_SMEM (2*SSTAGE*4)   // 81920 B

template<int MODE>
__global__ __launch_bounds__(256, 2)
void gemm_ts(const float* __restrict__ bo, float* __restrict__ outp) {
    extern __shared__ uint32_t smw[];
    int tid = threadIdx.x, lane = tid & 31;
    int warp = tid >> 5, warpM = warp >> 1, warpN = warp & 1;
    int z = (MODE == 0) ? (int)blockIdx.z : 3;
    int m0 = blockIdx.y*128, n0 = blockIdx.x*128;
    const __nv_bfloat16* Agh = (MODE == 0) ? ((z == 2) ? d_Xh : d_Xnh) : d_Ch;
    const __nv_bfloat16* Agl = (MODE == 0) ? ((z == 2) ? d_Xl : d_Xnl) : d_Cl;
    const __nv_bfloat16* Bgh = d_Wth[z];
    const __nv_bfloat16* Bgl = d_Wtl[z];
    uint32_t smbase = (uint32_t)__cvta_generic_to_shared(smw);

    int g = lane >> 3;
    int rowsel = (g >> 1)*8 + (lane & 7);
    int colsel = (g & 1)*4;

    float c[2][8][4];
    #pragma unroll
    for (int mt = 0; mt < 2; mt++)
        #pragma unroll
        for (int nt = 0; nt < 8; nt++)
            #pragma unroll
            for (int i = 0; i < 4; i++) c[mt][nt][i] = 0.f;

    // incrementally-advanced global pointers (8 cp16 per thread per chunk)
    int e0 = tid, e1 = tid + 256;
    int r0i = e0 >> 2, s0i = e0 & 3, r1i = e1 >> 2, s1i = e1 & 3;
    uint32_t w0 = (r0i*GT_ST + s0i*4)*4, w1 = (r1i*GT_ST + s1i*4)*4;
    const __nv_bfloat16* pAh0 = Agh + (size_t)(m0 + r0i)*DIM + s0i*8;
    const __nv_bfloat16* pAh1 = Agh + (size_t)(m0 + r1i)*DIM + s1i*8;
    const __nv_bfloat16* pAl0 = Agl + (size_t)(m0 + r0i)*DIM + s0i*8;
    const __nv_bfloat16* pAl1 = Agl + (size_t)(m0 + r1i)*DIM + s1i*8;
    const __nv_bfloat16* pBh0 = Bgh + (size_t)(n0 + r0i)*DIM + s0i*8;
    const __nv_bfloat16* pBh1 = Bgh + (size_t)(n0 + r1i)*DIM + s1i*8;
    const __nv_bfloat16* pBl0 = Bgl + (size_t)(n0 + r0i)*DIM + s0i*8;
    const __nv_bfloat16* pBl1 = Bgl + (size_t)(n0 + r1i)*DIM + s1i*8;

    // prologue: stage 0
    {
        uint32_t sb = smbase;
        cp16(sb + w0, pAh0);                 cp16(sb + w1, pAh1);
        cp16(sb + TILEW*4 + w0, pAl0);       cp16(sb + TILEW*4 + w1, pAl1);
        cp16(sb + 2*TILEW*4 + w0, pBh0);     cp16(sb + 2*TILEW*4 + w1, pBh1);
        cp16(sb + 3*TILEW*4 + w0, pBl0);     cp16(sb + 3*TILEW*4 + w1, pBl1);
        CP_COMMIT();
        pAh0 += 32; pAh1 += 32; pAl0 += 32; pAl1 += 32;
        pBh0 += 32; pBh1 += 32; pBl0 += 32; pBl1 += 32;
    }

    for (int ch = 0; ch < DIM/32; ch++) {
        CP_WAIT0();
        __syncthreads();   // single barrier per chunk (orders reads & next writes)

        if (ch + 1 < DIM/32) {
            uint32_t sb = smbase + ((ch + 1) & 1)*SSTAGE*4;
            cp16(sb + w0, pAh0);                 cp16(sb + w1, pAh1);
            cp16(sb + TILEW*4 + w0, pAl0);       cp16(sb + TILEW*4 + w1, pAl1);
            cp16(sb + 2*TILEW*4 + w0, pBh0);     cp16(sb + 2*TILEW*4 + w1, pBh1);
            cp16(sb + 3*TILEW*4 + w0, pBl0);     cp16(sb + 3*TILEW*4 + w1, pBl1);
            CP_COMMIT();
            pAh0 += 32; pAh1 += 32; pAl0 += 32; pAl1 += 32;
            pBh0 += 32; pBh1 += 32; pBl0 += 32; pBl1 += 32;
        }

        uint32_t st = smbase + (ch & 1)*SSTAGE*4;
        uint32_t AHb = st, ALb = st + TILEW*4, BHb = st + 2*TILEW*4, BLb = st + 3*TILEW*4;

        #pragma unroll
        for (int k16 = 0; k16 < 2; k16++) {
            uint32_t koff = (k16*8 + colsel)*4;
            uint32_t ah[2][4], al[2][4];
            #pragma unroll
            for (int mt = 0; mt < 2; mt++) {
                uint32_t aoff = ((warpM*32 + mt*16 + rowsel)*GT_ST)*4 + koff;
                uint32_t t4[4];
                ldsm4(t4, AHb + aoff);
                ah[mt][0] = t4[0]; ah[mt][1] = t4[2]; ah[mt][2] = t4[1]; ah[mt][3] = t4[3];
                ldsm4(t4, ALb + aoff);
                al[mt][0] = t4[0]; al[mt][1] = t4[2]; al[mt][2] = t4[1]; al[mt][3] = t4[3];
            }
            // software-pipelined B fragments: load ntp+1 before computing ntp
            uint32_t bh[2][4], bl[2][4];
            {
                uint32_t boff = ((warpN*64 + rowsel)*GT_ST)*4 + koff;
                ldsm4(bh[0], BHb + boff);
                ldsm4(bl[0], BLb + boff);
            }
            #pragma unroll
            for (int ntp = 0; ntp < 4; ntp++) {
                int cur = ntp & 1, nxt = cur ^ 1;
                if (ntp < 3) {
                    uint32_t boff = ((warpN*64 + (ntp+1)*16 + rowsel)*GT_ST)*4 + koff;
                    ldsm4(bh[nxt], BHb + boff);
                    ldsm4(bl[nxt], BLb + boff);
                }
                #pragma unroll
                for (int mt = 0; mt < 2; mt++) {
                    mma_bf16(c[mt][2*ntp],   ah[mt], bh[cur]);
                    mma_bf16(c[mt][2*ntp],   ah[mt], bl[cur]);
                    mma_bf16(c[mt][2*ntp],   al[mt], bh[cur]);
                    mma_bf16(c[mt][2*ntp+1], ah[mt], bh[cur] + 2);
                    mma_bf16(c[mt][2*ntp+1], ah[mt], bl[cur] + 2);
                    mma_bf16(c[mt][2*ntp+1], al[mt], bh[cur] + 2);
                }
            }
        }
        // no bottom barrier: next iteration's top barrier provides the ordering
    }

    #pragma unroll
    for (int mt = 0; mt < 2; mt++) {
        #pragma unroll
        for (int nt = 0; nt < 8; nt++) {
            int row = m0 + warpM*32 + mt*16 + (lane >> 2);
            int col = n0 + warpN*64 + nt*8 + (lane & 3)*2;
            #pragma unroll
            for (int half = 0; half < 2; half++) {
                int r = row + half*8;
                float2 v = make_float2(c[mt][nt][half*2], c[mt][nt][half*2+1]);
                if (MODE == 0) {
                    float* dst = (z == 0) ? d_Q : (z == 1) ? d_K : d_V;
                    int b = r >> 11, t = r & 2047;
                    int h = col >> 6, dd = col & 63;
                    *(float2*)&dst[(((size_t)(b*HEADS + h))*TLEN + t)*HD + dd] = v;
                } else {
                    v.x += bo[col]; v.y += bo[col+1];
                    *(float2*)&outp[(size_t)r*DIM + col] = v;
                }
            }
        }
    }
}

// ------- L2 normalize + gates + bf16 hi/lo split (validated R7) --------------
__global__ void normgate_kernel(const float* __restrict__ gqv,
                                const float* __restrict__ gkv) {
    int r = (blockIdx.x*blockDim.x + threadIdx.x) >> 5;
    int lane = threadIdx.x & 31;
    if (r >= HROWS) return;
    const float* q = d_Q + (size_t)r*HD;
    const float* k = d_K + (size_t)r*HD;
    const float* v = d_V + (size_t)r*HD;

    float q0 = q[lane], q1 = q[lane+32];
    float ss = q0*q0 + q1*q1;
    #pragma unroll
    for (int o = 16; o > 0; o >>= 1) ss += __shfl_xor_sync(~0u, ss, o);
    float inv = 1.0f / fmaxf(sqrtf(ss), 1e-12f);
    q0 *= inv; q1 *= inv;
    __nv_bfloat16 h0, l0, h1, l1;
    bf_split(q0, h0, l0); bf_split(q1, h1, l1);
    d_Qh[(size_t)r*HD + lane] = h0;       d_Ql[(size_t)r*HD + lane] = l0;
    d_Qh[(size_t)r*HD + lane + 32] = h1;  d_Ql[(size_t)r*HD + lane + 32] = l1;
    float g = q0*gqv[lane] + q1*gqv[lane+32];
    #pragma unroll
    for (int o = 16; o > 0; o >>= 1) g += __shfl_xor_sync(~0u, g, o);
    if (lane == 0) d_gq[r] = g;

    float k0 = k[lane], k1 = k[lane+32];
    ss = k0*k0 + k1*k1;
    #pragma unroll
    for (int o = 16; o > 0; o >>= 1) ss += __shfl_xor_sync(~0u, ss, o);
    inv = 1.0f / fmaxf(sqrtf(ss), 1e-12f);
    k0 *= inv; k1 *= inv;
    bf_split(k0, h0, l0); bf_split(k1, h1, l1);
    d_Kh[(size_t)r*HD + lane] = h0;       d_Kl[(size_t)r*HD + lane] = l0;
    d_Kh[(size_t)r*HD + lane + 32] = h1;  d_Kl[(size_t)r*HD + lane + 32] = l1;
    float gk = k0*gkv[lane] + k1*gkv[lane+32];
    #pragma unroll
    for (int o = 16; o > 0; o >>= 1) gk += __shfl_xor_sync(~0u, gk, o);

    int head = r >> 11, sl = r & 2047;
    size_t vbase = (size_t)head*HD*TLEN;
    float v0 = v[lane]*gk, v1 = v[lane+32]*gk;
    bf_split(v0, h0, l0); bf_split(v1, h1, l1);
    d_Vth[vbase + (size_t)lane*TLEN + sl] = h0;
    d_Vtl[vbase + (size_t)lane*TLEN + sl] = l0;
    d_Vth[vbase + (size_t)(lane+32)*TLEN + sl] = h1;
    d_Vtl[vbase + (size_t)(lane+32)*TLEN + sl] = l1;
}

// --- bf16x3 attention (validated R12/R13) ------------------------------------
#define ST 36
#define WQH 0
#define WQL (128*ST)
#define KV0 (2*128*ST)
#define KVSTAGE (4*64*ST)
#define ATT_SMEM ((2*128*ST + 2*KVSTAGE)*4)

__global__ __launch_bounds__(256, 2)
void attn_tc() {
    extern __shared__ uint32_t smw[];
    __shared__ float gqs[128];
    int tid = threadIdx.x, lane = tid & 31;
    int warp = tid >> 5;
    int h = blockIdx.y, b = blockIdx.z;
    int t0 = blockIdx.x * 128;
    int head = b*HEADS + h;
    size_t base = (size_t)head*TLEN;
    uint32_t smbase = (uint32_t)__cvta_generic_to_shared(smw);

    int g = lane >> 3;
    int rowsel = (g >> 1)*8 + (lane & 7);
    int colsel = (g & 1)*4;

    {
        const uint4* qh = (const uint4*)(d_Qh + (base + t0)*HD);
        const uint4* ql = (const uint4*)(d_Ql + (base + t0)*HD);
        #pragma unroll
        for (int j = 0; j < 4; j++) {
            int e = tid + 256*j;
            int t = e >> 3, q4 = (e & 7)*4;
            *(uint4*)&smw[WQH + t*ST + q4] = qh[e];
            *(uint4*)&smw[WQL + t*ST + q4] = ql[e];
        }
    }
    if (tid < 128) gqs[tid] = d_gq[base + t0 + tid];

    const char* khg = (const char*)(d_Kh + base*HD);
    const char* klg = (const char*)(d_Kl + base*HD);
    const char* vhg = (const char*)(d_Vth + (size_t)head*HD*TLEN);
    const char* vlg = (const char*)(d_Vtl + (size_t)head*HD*TLEN);
    int e0 = tid, e1 = tid + 256;
    int rr0 = e0 >> 3, q40 = (e0 & 7), rr1 = e1 >> 3, q41 = (e1 & 7);
    uint32_t soff0 = (rr0*ST + q40*4)*4, soff1 = (rr1*ST + q41*4)*4;
    size_t voff0 = ((size_t)rr0*(TLEN/8) + q40)*16;
    size_t voff1 = ((size_t)rr1*(TLEN/8) + q41)*16;

    {
        uint32_t kvb = smbase + KV0*4;
        cp16(kvb + soff0, khg + (size_t)e0*16);
        cp16(kvb + soff1, khg + (size_t)e1*16);
        cp16(kvb + 64*ST*4 + soff0, klg + (size_t)e0*16);
        cp16(kvb + 64*ST*4 + soff1, klg + (size_t)e1*16);
        cp16(kvb + 2*64*ST*4 + soff0, vhg + voff0);
        cp16(kvb + 2*64*ST*4 + soff1, vhg + voff1);
        cp16(kvb + 3*64*ST*4 + soff0, vlg + voff0);
        cp16(kvb + 3*64*ST*4 + soff1, vlg + voff1);
        CP_COMMIT();
    }
    __syncthreads();

    int rA = warp*16 + (lane >> 2);
    uint32_t qfh[4][4], qfl[4][4];
    #pragma unroll
    for (int k16 = 0; k16 < 4; k16++) {
        int cw = k16*8 + (lane & 3);
        qfh[k16][0] = smw[WQH + rA*ST + cw];
        qfh[k16][1] = smw[WQH + (rA+8)*ST + cw];
        qfh[k16][2] = smw[WQH + rA*ST + cw + 4];
        qfh[k16][3] = smw[WQH + (rA+8)*ST + cw + 4];
        qfl[k16][0] = smw[WQL + rA*ST + cw];
        qfl[k16][1] = smw[WQL + (rA+8)*ST + cw];
        qfl[k16][2] = smw[WQL + rA*ST + cw + 4];
        qfl[k16][3] = smw[WQL + (rA+8)*ST + cw + 4];
    }

    float acc[8][4];
    #pragma unroll
    for (int nt = 0; nt < 8; nt++)
        #pragma unroll
        for (int i = 0; i < 4; i++) acc[nt][i] = 0.f;

    const float ZOFF = -THRESH * SHARP;

    for (int it = 0; it < TLEN/64; it++) {
        CP_WAIT0();
        __syncthreads();

        if (it + 1 < TLEN/64) {
            size_t s0n = (size_t)(it + 1)*64;
            uint32_t kvb = smbase + (KV0 + ((it+1)&1)*KVSTAGE)*4;
            size_t koff = s0n*HD*2;
            cp16(kvb + soff0, khg + koff + (size_t)e0*16);
            cp16(kvb + soff1, khg + koff + (size_t)e1*16);
            cp16(kvb + 64*ST*4 + soff0, klg + koff + (size_t)e0*16);
            cp16(kvb + 64*ST*4 + soff1, klg + koff + (size_t)e1*16);
            size_t vcoff = s0n*2;
            cp16(kvb + 2*64*ST*4 + soff0, vhg + vcoff + voff0);
            cp16(kvb + 2*64*ST*4 + soff1, vhg + vcoff + voff1);
            cp16(kvb + 3*64*ST*4 + soff0, vlg + vcoff + voff0);
            cp16(kvb + 3*64*ST*4 + soff1, vlg + vcoff + voff1);
            CP_COMMIT();
        }

        int kvw = KV0 + (it & 1)*KVSTAGE;
        uint32_t KHb = smbase + kvw*4;
        uint32_t KLb = KHb + 64*ST*4;
        uint32_t VHb = KHb + 2*64*ST*4;
        uint32_t VLb = KHb + 3*64*ST*4;

        float c[8][4];
        #pragma unroll
        for (int nt = 0; nt < 8; nt++)
            #pragma unroll
            for (int i = 0; i < 4; i++) c[nt][i] = 0.f;

        #pragma unroll
        for (int k16 = 0; k16 < 4; k16++) {
            #pragma unroll
            for (int ntp = 0; ntp < 4; ntp++) {
                uint32_t aoff = ((ntp*16 + rowsel)*ST + k16*8 + colsel)*4;
                uint32_t bh[4], bl[4];
                ldsm4(bh, KHb + aoff);
                ldsm4(bl, KLb + aoff);
                mma_bf16(c[2*ntp],   qfh[k16], bh);
                mma_bf16(c[2*ntp],   qfh[k16], bl);
                mma_bf16(c[2*ntp],   qfl[k16], bh);
                mma_bf16(c[2*ntp+1], qfh[k16], bh + 2);
                mma_bf16(c[2*ntp+1], qfh[k16], bl + 2);
                mma_bf16(c[2*ntp+1], qfl[k16], bh + 2);
            }
        }

        uint32_t ph[8][2], pl[8][2];
        #pragma unroll
        for (int nt = 0; nt < 8; nt++)
            #pragma unroll
            for (int half = 0; half < 2; half++) {
                float z0 = fmaf(c[nt][half*2],   SHARP, ZOFF);
                float z1 = fmaf(c[nt][half*2+1], SHARP, ZOFF);
                float p0 = __fdividef(1.0f, 1.0f + __expf(-z0));
                float p1 = __fdividef(1.0f, 1.0f + __expf(-z1));
                ph[nt][half] = bfpack2(p0, p1);
                pl[nt][half] = bfpack2(bflo(p0), bflo(p1));
            }

        #pragma unroll
        for (int k16 = 0; k16 < 4; k16++) {
            uint32_t ah[4] = { ph[2*k16][0], ph[2*k16][1], ph[2*k16+1][0], ph[2*k16+1][1] };
            uint32_t al[4] = { pl[2*k16][0], pl[2*k16][1], pl[2*k16+1][0], pl[2*k16+1][1] };
            #pragma unroll
            for (int ntp = 0; ntp < 4; ntp++) {
                uint32_t aoff = ((ntp*16 + rowsel)*ST + k16*8 + colsel)*4;
                uint32_t bh[4], bl[4];
                ldsm4(bh, VHb + aoff);
                ldsm4(bl, VLb + aoff);
                mma_bf16(acc[2*ntp],   ah, bh);
                mma_bf16(acc[2*ntp],   ah, bl);
                mma_bf16(acc[2*ntp],   al, bh);
                mma_bf16(acc[2*ntp+1], ah, bh + 2);
                mma_bf16(acc[2*ntp+1], ah, bl + 2);
                mma_bf16(acc[2*ntp+1], al, bh + 2);
            }
        }
    }

    size_t cb = ((size_t)(b*TLEN) + t0)*DIM + h*HD;
    #pragma unroll
    for (int nt = 0; nt < 8; nt++)
        #pragma unroll
        for (int half = 0; half < 2; half++) {
            int row = warp*16 + (lane >> 2) + half*8;
            int col = nt*8 + (lane & 3)*2;
            float g2 = gqs[row];
            float v0 = acc[nt][half*2]*g2, v1 = acc[nt][half*2+1]*g2;
            size_t off = cb + (size_t)row*DIM + col;
            *(uint32_t*)&d_Ch[off] = bfpack2(v0, v1);
            *(uint32_t*)&d_Cl[off] = bfpack2(bflo(v0), bflo(v1));
        }
}

// ---------------- launch ------------------------------------------------------
extern "C" void kernel_launch(void* const* d_in, const int* in_sizes, int n_in,
                              void* d_out, int out_size) {
    const float* x   = (const float*)d_in[0];
    const float* Wq  = (const float*)d_in[1];
    const float* Wk  = (const float*)d_in[2];
    const float* Wv  = (const float*)d_in[3];
    const float* gqv = (const float*)d_in[4];
    const float* gkv = (const float*)d_in[5];
    const float* Wo  = (const float*)d_in[6];
    const float* bo  = (const float*)d_in[7];
    const float* lnw = (const float*)d_in[8];
    const float* lnb = (const float*)d_in[9];
    float* out = (float*)d_out;

    cudaFuncSetAttribute(attn_tc, cudaFuncAttributeMaxDynamicSharedMemorySize, ATT_SMEM);
    cudaFuncSetAttribute(gemm_ts<0>, cudaFuncAttributeMaxDynamicSharedMemorySize, GEMM_SMEM);
    cudaFuncSetAttribute(gemm_ts<1>, cudaFuncAttributeMaxDynamicSharedMemorySize, GEMM_SMEM);

    ln_kernel<<<ROWS, 256>>>(x, lnw, lnb);
    split_x<<<ROWS*DIM/1024, 256>>>(x);
    wsplit<<<dim3(32, 32, 4), dim3(32, 8)>>>(Wq, Wk, Wv, Wo);
    gemm_ts<0><<<dim3(8, 32, 3), 256, GEMM_SMEM>>>(nullptr, nullptr);
    normgate_kernel<<<HROWS*32/256, 256>>>(gqv, gkv);
    attn_tc<<<dim3(TLEN/128, HEADS, BATCH), 256, ATT_SMEM>>>();
    gemm_ts<1><<<dim3(8, 32), 256, GEMM_SMEM>>>(bo, out);
}

// round 15
// speedup vs baseline: 1.5754x; 1.5754x over previous
#include <cuda_runtime.h>
#include <cuda_bf16.h>
#include <cstdint>
#include <math.h>

#define DIM    1024
#define BATCH  2
#define TLEN   2048
#define HEADS  16
#define HD     64
#define ROWS   (BATCH*TLEN)
#define HROWS  (BATCH*HEADS*TLEN)
#define THRESH 0.29514f
#define SHARP  15.0f

__device__ float d_Q[HROWS*HD];
__device__ float d_K[HROWS*HD];
__device__ float d_V[HROWS*HD];
__device__ float d_gq[HROWS];
__device__ __align__(16) __nv_bfloat16 d_Qh[HROWS*HD];
__device__ __align__(16) __nv_bfloat16 d_Ql[HROWS*HD];
__device__ __align__(16) __nv_bfloat16 d_Kh[HROWS*HD];
__device__ __align__(16) __nv_bfloat16 d_Kl[HROWS*HD];
__device__ __align__(16) __nv_bfloat16 d_Vth[HROWS*HD];  // [b,h][d][s]
__device__ __align__(16) __nv_bfloat16 d_Vtl[HROWS*HD];
__device__ __align__(16) __nv_bfloat16 d_Wth[4][DIM*DIM];
__device__ __align__(16) __nv_bfloat16 d_Wtl[4][DIM*DIM];
__device__ __align__(16) __nv_bfloat16 d_Xnh[ROWS*DIM];
__device__ __align__(16) __nv_bfloat16 d_Xnl[ROWS*DIM];
__device__ __align__(16) __nv_bfloat16 d_Xh[ROWS*DIM];
__device__ __align__(16) __nv_bfloat16 d_Xl[ROWS*DIM];
__device__ __align__(16) __nv_bfloat16 d_Ch[ROWS*DIM];
__device__ __align__(16) __nv_bfloat16 d_Cl[ROWS*DIM];

// ---------------- mma.sync / helpers ----------------
__device__ __forceinline__ void mma_bf16(float* c, const uint32_t* a, const uint32_t* b) {
    asm volatile(
        "mma.sync.aligned.m16n8k16.row.col.f32.bf16.bf16.f32 "
        "{%0,%1,%2,%3}, {%4,%5,%6,%7}, {%8,%9}, {%0,%1,%2,%3};"
        : "+f"(c[0]), "+f"(c[1]), "+f"(c[2]), "+f"(c[3])
        : "r"(a[0]), "r"(a[1]), "r"(a[2]), "r"(a[3]), "r"(b[0]), "r"(b[1]));
}
__device__ __forceinline__ void ldsm4(uint32_t* r, uint32_t addr) {
    asm volatile("ldmatrix.sync.aligned.m8n8.x4.shared.b16 {%0,%1,%2,%3}, [%4];"
                 : "=r"(r[0]), "=r"(r[1]), "=r"(r[2]), "=r"(r[3]) : "r"(addr));
}
__device__ __forceinline__ uint32_t bfpack2(float a, float b) {
    __nv_bfloat162 p = __floats2bfloat162_rn(a, b);
    return *reinterpret_cast<uint32_t*>(&p);
}
__device__ __forceinline__ float bflo(float v) {
    return v - __bfloat162float(__float2bfloat16_rn(v));
}
__device__ __forceinline__ void bf_split(float v, __nv_bfloat16& h, __nv_bfloat16& l) {
    h = __float2bfloat16_rn(v);
    l = __float2bfloat16_rn(v - __bfloat162float(h));
}
__device__ __forceinline__ void cp16(uint32_t smem_addr, const void* gptr) {
    asm volatile("cp.async.cg.shared.global [%0], [%1], 16;"
                 :: "r"(smem_addr), "l"(gptr) : "memory");
}
#define CP_COMMIT() asm volatile("cp.async.commit_group;" ::: "memory")
#define CP_WAIT0()  asm volatile("cp.async.wait_group 0;" ::: "memory")

// ---------------- LayerNorm (+ bf16 hi/lo split of xnorm) --------------------
__global__ void ln_kernel(const float* __restrict__ x,
                          const float* __restrict__ w,
                          const float* __restrict__ bvec) {
    int row = blockIdx.x, tid = threadIdx.x;
    float4 v = ((const float4*)(x + (size_t)row*DIM))[tid];
    float s  = v.x+v.y+v.z+v.w;
    float ss = v.x*v.x+v.y*v.y+v.z*v.z+v.w*v.w;
    #pragma unroll
    for (int o = 16; o > 0; o >>= 1) {
        s  += __shfl_xor_sync(~0u, s, o);
        ss += __shfl_xor_sync(~0u, ss, o);
    }
    __shared__ float rs[8], rss[8];
    int wid = tid >> 5, lane = tid & 31;
    if (lane == 0) { rs[wid] = s; rss[wid] = ss; }
    __syncthreads();
    s = 0.f; ss = 0.f;
    #pragma unroll
    for (int i = 0; i < 8; i++) { s += rs[i]; ss += rss[i]; }
    float mean = s*(1.f/DIM), var = ss*(1.f/DIM) - mean*mean;
    float rstd = rsqrtf(var + 1e-5f);
    float4 wv = ((const float4*)w)[tid], bv = ((const float4*)bvec)[tid];
    float4 o;
    o.x = (v.x-mean)*rstd*wv.x + bv.x;  o.y = (v.y-mean)*rstd*wv.y + bv.y;
    o.z = (v.z-mean)*rstd*wv.z + bv.z;  o.w = (v.w-mean)*rstd*wv.w + bv.w;
    uint2 hw = make_uint2(bfpack2(o.x, o.y), bfpack2(o.z, o.w));
    uint2 lw = make_uint2(bfpack2(bflo(o.x), bflo(o.y)), bfpack2(bflo(o.z), bflo(o.w)));
    *(uint2*)&d_Xnh[(size_t)row*DIM + tid*4] = hw;
    *(uint2*)&d_Xnl[(size_t)row*DIM + tid*4] = lw;
}

// ---------------- split x into bf16 hi/lo ----------------
__global__ void split_x(const float* __restrict__ x) {
    int i = (blockIdx.x*256 + threadIdx.x)*4;
    float4 v = *(const float4*)(x + i);
    *(uint2*)&d_Xh[i] = make_uint2(bfpack2(v.x, v.y), bfpack2(v.z, v.w));
    *(uint2*)&d_Xl[i] = make_uint2(bfpack2(bflo(v.x), bflo(v.y)), bfpack2(bflo(v.z), bflo(v.w)));
}

// ---------------- weight transpose + split: Wt[z][n][k] ----------------------
__global__ void wsplit(const float* __restrict__ Wq, const float* __restrict__ Wk,
                       const float* __restrict__ Wv, const float* __restrict__ Wo) {
    __shared__ float tile[32][33];
    int z = blockIdx.z;
    const float* W = (z==0) ? Wq : (z==1) ? Wk : (z==2) ? Wv : Wo;
    int n0 = blockIdx.x*32, k0 = blockIdx.y*32;
    int tx = threadIdx.x, ty = threadIdx.y;
    #pragma unroll
    for (int i = 0; i < 4; i++)
        tile[ty+8*i][tx] = W[(size_t)(k0+ty+8*i)*DIM + n0 + tx];
    __syncthreads();
    #pragma unroll
    for (int i = 0; i < 4; i++) {
        float v = tile[tx][ty+8*i];
        __nv_bfloat16 h, l;
        bf_split(v, h, l);
        d_Wth[z][(size_t)(n0+ty+8*i)*DIM + k0 + tx] = h;
        d_Wtl[z][(size_t)(n0+ty+8*i)*DIM + k0 + tx] = l;
    }
}

// -------- bf16x3 GEMM (R13 layout, single barrier per chunk) -----------------
#define GT_ST 20
#define TILEW (128*GT_ST)
#define SSTAGE (4*TILEW)
#define GEMM_SMEM (2*SSTAGE*4)   // 81920 B

template<int MODE>
__global__ __launch_bounds__(256, 2)
void gemm_ts(const float* __restrict__ bo, float* __restrict__ outp) {
    extern __shared__ uint32_t smw[];
    int tid = threadIdx.x, lane = tid & 31;
    int warp = tid >> 5, warpM = warp >> 1, warpN = warp & 1;
    int z = (MODE == 0) ? (int)blockIdx.z : 3;
    int m0 = blockIdx.y*128, n0 = blockIdx.x*128;
    const __nv_bfloat16* Agh = (MODE == 0) ? ((z == 2) ? d_Xh : d_Xnh) : d_Ch;
    const __nv_bfloat16* Agl = (MODE == 0) ? ((z == 2) ? d_Xl : d_Xnl) : d_Cl;
    const __nv_bfloat16* Bgh = d_Wth[z];
    const __nv_bfloat16* Bgl = d_Wtl[z];
    uint32_t smbase = (uint32_t)__cvta_generic_to_shared(smw);

    int g = lane >> 3;
    int rowsel = (g >> 1)*8 + (lane & 7);
    int colsel = (g & 1)*4;

    float c[2][8][4];
    #pragma unroll
    for (int mt = 0; mt < 2; mt++)
        #pragma unroll
        for (int nt = 0; nt < 8; nt++)
            #pragma unroll
            for (int i = 0; i < 4; i++) c[mt][nt][i] = 0.f;

    // cp.async indexing (R13 scheme: recomputed per chunk, no extra pointers)
    int e0 = tid, e1 = tid + 256;
    int r0i = e0 >> 2, s0i = e0 & 3, r1i = e1 >> 2, s1i = e1 & 3;
    uint32_t w0 = (r0i*GT_ST + s0i*4)*4, w1 = (r1i*GT_ST + s1i*4)*4;
    size_t a0g = (size_t)(m0 + r0i)*DIM + s0i*8, a1g = (size_t)(m0 + r1i)*DIM + s1i*8;
    size_t b0g = (size_t)(n0 + r0i)*DIM + s0i*8, b1g = (size_t)(n0 + r1i)*DIM + s1i*8;

    // prologue: stage 0
    {
        uint32_t sb = smbase;
        cp16(sb + w0, Agh + a0g);                 cp16(sb + w1, Agh + a1g);
        cp16(sb + TILEW*4 + w0, Agl + a0g);       cp16(sb + TILEW*4 + w1, Agl + a1g);
        cp16(sb + 2*TILEW*4 + w0, Bgh + b0g);     cp16(sb + 2*TILEW*4 + w1, Bgh + b1g);
        cp16(sb + 3*TILEW*4 + w0, Bgl + b0g);     cp16(sb + 3*TILEW*4 + w1, Bgl + b1g);
        CP_COMMIT();
    }

    for (int ch = 0; ch < DIM/32; ch++) {
        CP_WAIT0();
        __syncthreads();   // single barrier per chunk

        if (ch + 1 < DIM/32) {
            int k0 = (ch + 1)*32;
            uint32_t sb = smbase + ((ch + 1) & 1)*SSTAGE*4;
            cp16(sb + w0, Agh + a0g + k0);             cp16(sb + w1, Agh + a1g + k0);
            cp16(sb + TILEW*4 + w0, Agl + a0g + k0);   cp16(sb + TILEW*4 + w1, Agl + a1g + k0);
            cp16(sb + 2*TILEW*4 + w0, Bgh + b0g + k0); cp16(sb + 2*TILEW*4 + w1, Bgh + b1g + k0);
            cp16(sb + 3*TILEW*4 + w0, Bgl + b0g + k0); cp16(sb + 3*TILEW*4 + w1, Bgl + b1g + k0);
            CP_COMMIT();
        }

        uint32_t st = smbase + (ch & 1)*SSTAGE*4;
        uint32_t AHb = st, ALb = st + TILEW*4, BHb = st + 2*TILEW*4, BLb = st + 3*TILEW*4;

        #pragma unroll
        for (int k16 = 0; k16 < 2; k16++) {
            uint32_t koff = (k16*8 + colsel)*4;
            uint32_t ah[2][4], al[2][4];
            #pragma unroll
            for (int mt = 0; mt < 2; mt++) {
                uint32_t aoff = ((warpM*32 + mt*16 + rowsel)*GT_ST)*4 + koff;
                uint32_t t4[4];
                ldsm4(t4, AHb + aoff);
                ah[mt][0] = t4[0]; ah[mt][1] = t4[2]; ah[mt][2] = t4[1]; ah[mt][3] = t4[3];
                ldsm4(t4, ALb + aoff);
                al[mt][0] = t4[0]; al[mt][1] = t4[2]; al[mt][2] = t4[1]; al[mt][3] = t4[3];
            }
            #pragma unroll
            for (int ntp = 0; ntp < 4; ntp++) {
                uint32_t boff = ((warpN*64 + ntp*16 + rowsel)*GT_ST)*4 + koff;
                uint32_t bh[4], bl[4];
                ldsm4(bh, BHb + boff);
                ldsm4(bl, BLb + boff);
                #pragma unroll
                for (int mt = 0; mt < 2; mt++) {
                    mma_bf16(c[mt][2*ntp],   ah[mt], bh);
                    mma_bf16(c[mt][2*ntp],   ah[mt], bl);
                    mma_bf16(c[mt][2*ntp],   al[mt], bh);
                    mma_bf16(c[mt][2*ntp+1], ah[mt], bh + 2);
                    mma_bf16(c[mt][2*ntp+1], ah[mt], bl + 2);
                    mma_bf16(c[mt][2*ntp+1], al[mt], bh + 2);
                }
            }
        }
        // no bottom barrier: next iteration's CP_WAIT0 + top barrier order reads/writes
    }

    #pragma unroll
    for (int mt = 0; mt < 2; mt++) {
        #pragma unroll
        for (int nt = 0; nt < 8; nt++) {
            int row = m0 + warpM*32 + mt*16 + (lane >> 2);
            int col = n0 + warpN*64 + nt*8 + (lane & 3)*2;
            #pragma unroll
            for (int half = 0; half < 2; half++) {
                int r = row + half*8;
                float2 v = make_float2(c[mt][nt][half*2], c[mt][nt][half*2+1]);
                if (MODE == 0) {
                    float* dst = (z == 0) ? d_Q : (z == 1) ? d_K : d_V;
                    int b = r >> 11, t = r & 2047;
                    int h = col >> 6, dd = col & 63;
                    *(float2*)&dst[(((size_t)(b*HEADS + h))*TLEN + t)*HD + dd] = v;
                } else {
                    v.x += bo[col]; v.y += bo[col+1];
                    *(float2*)&outp[(size_t)r*DIM + col] = v;
                }
            }
        }
    }
}

// ------- L2 normalize + gates + bf16 hi/lo split (validated R7) --------------
__global__ void normgate_kernel(const float* __restrict__ gqv,
                                const float* __restrict__ gkv) {
    int r = (blockIdx.x*blockDim.x + threadIdx.x) >> 5;
    int lane = threadIdx.x & 31;
    if (r >= HROWS) return;
    const float* q = d_Q + (size_t)r*HD;
    const float* k = d_K + (size_t)r*HD;
    const float* v = d_V + (size_t)r*HD;

    float q0 = q[lane], q1 = q[lane+32];
    float ss = q0*q0 + q1*q1;
    #pragma unroll
    for (int o = 16; o > 0; o >>= 1) ss += __shfl_xor_sync(~0u, ss, o);
    float inv = 1.0f / fmaxf(sqrtf(ss), 1e-12f);
    q0 *= inv; q1 *= inv;
    __nv_bfloat16 h0, l0, h1, l1;
    bf_split(q0, h0, l0); bf_split(q1, h1, l1);
    d_Qh[(size_t)r*HD + lane] = h0;       d_Ql[(size_t)r*HD + lane] = l0;
    d_Qh[(size_t)r*HD + lane + 32] = h1;  d_Ql[(size_t)r*HD + lane + 32] = l1;
    float g = q0*gqv[lane] + q1*gqv[lane+32];
    #pragma unroll
    for (int o = 16; o > 0; o >>= 1) g += __shfl_xor_sync(~0u, g, o);
    if (lane == 0) d_gq[r] = g;

    float k0 = k[lane], k1 = k[lane+32];
    ss = k0*k0 + k1*k1;
    #pragma unroll
    for (int o = 16; o > 0; o >>= 1) ss += __shfl_xor_sync(~0u, ss, o);
    inv = 1.0f / fmaxf(sqrtf(ss), 1e-12f);
    k0 *= inv; k1 *= inv;
    bf_split(k0, h0, l0); bf_split(k1, h1, l1);
    d_Kh[(size_t)r*HD + lane] = h0;       d_Kl[(size_t)r*HD + lane] = l0;
    d_Kh[(size_t)r*HD + lane + 32] = h1;  d_Kl[(size_t)r*HD + lane + 32] = l1;
    float gk = k0*gkv[lane] + k1*gkv[lane+32];
    #pragma unroll
    for (int o = 16; o > 0; o >>= 1) gk += __shfl_xor_sync(~0u, gk, o);

    int head = r >> 11, sl = r & 2047;
    size_t vbase = (size_t)head*HD*TLEN;
    float v0 = v[lane]*gk, v1 = v[lane+32]*gk;
    bf_split(v0, h0, l0); bf_split(v1, h1, l1);
    d_Vth[vbase + (size_t)lane*TLEN + sl] = h0;
    d_Vtl[vbase + (size_t)lane*TLEN + sl] = l0;
    d_Vth[vbase + (size_t)(lane+32)*TLEN + sl] = h1;
    d_Vtl[vbase + (size_t)(lane+32)*TLEN + sl] = l1;
}

// --- bf16x3 attention (validated R12/R13) ------------------------------------
#define ST 36
#define WQH 0
#define WQL (128*ST)
#define KV0 (2*128*ST)
#define KVSTAGE (4*64*ST)
#define ATT_SMEM ((2*128*ST + 2*KVSTAGE)*4)

__global__ __launch_bounds__(256, 2)
void attn_tc() {
    extern __shared__ uint32_t smw[];
    __shared__ float gqs[128];
    int tid = threadIdx.x, lane = tid & 31;
    int warp = tid >> 5;
    int h = blockIdx.y, b = blockIdx.z;
    int t0 = blockIdx.x * 128;
    int head = b*HEADS + h;
    size_t base = (size_t)head*TLEN;
    uint32_t smbase = (uint32_t)__cvta_generic_to_shared(smw);

    int g = lane >> 3;
    int rowsel = (g >> 1)*8 + (lane & 7);
    int colsel = (g & 1)*4;

    {
        const uint4* qh = (const uint4*)(d_Qh + (base + t0)*HD);
        const uint4* ql = (const uint4*)(d_Ql + (base + t0)*HD);
        #pragma unroll
        for (int j = 0; j < 4; j++) {
            int e = tid + 256*j;
            int t = e >> 3, q4 = (e & 7)*4;
            *(uint4*)&smw[WQH + t*ST + q4] = qh[e];
            *(uint4*)&smw[WQL + t*ST + q4] = ql[e];
        }
    }
    if (tid < 128) gqs[tid] = d_gq[base + t0 + tid];

    const char* khg = (const char*)(d_Kh + base*HD);
    const char* klg = (const char*)(d_Kl + base*HD);
    const char* vhg = (const char*)(d_Vth + (size_t)head*HD*TLEN);
    const char* vlg = (const char*)(d_Vtl + (size_t)head*HD*TLEN);
    int e0 = tid, e1 = tid + 256;
    int rr0 = e0 >> 3, q40 = (e0 & 7), rr1 = e1 >> 3, q41 = (e1 & 7);
    uint32_t soff0 = (rr0*ST + q40*4)*4, soff1 = (rr1*ST + q41*4)*4;
    size_t voff0 = ((size_t)rr0*(TLEN/8) + q40)*16;
    size_t voff1 = ((size_t)rr1*(TLEN/8) + q41)*16;

    {
        uint32_t kvb = smbase + KV0*4;
        cp16(kvb + soff0, khg + (size_t)e0*16);
        cp16(kvb + soff1, khg + (size_t)e1*16);
        cp16(kvb + 64*ST*4 + soff0, klg + (size_t)e0*16);
        cp16(kvb + 64*ST*4 + soff1, klg + (size_t)e1*16);
        cp16(kvb + 2*64*ST*4 + soff0, vhg + voff0);
        cp16(kvb + 2*64*ST*4 + soff1, vhg + voff1);
        cp16(kvb + 3*64*ST*4 + soff0, vlg + voff0);
        cp16(kvb + 3*64*ST*4 + soff1, vlg + voff1);
        CP_COMMIT();
    }
    __syncthreads();

    int rA = warp*16 + (lane >> 2);
    uint32_t qfh[4][4], qfl[4][4];
    #pragma unroll
    for (int k16 = 0; k16 < 4; k16++) {
        int cw = k16*8 + (lane & 3);
        qfh[k16][0] = smw[WQH + rA*ST + cw];
        qfh[k16][1] = smw[WQH + (rA+8)*ST + cw];
        qfh[k16][2] = smw[WQH + rA*ST + cw + 4];
        qfh[k16][3] = smw[WQH + (rA+8)*ST + cw + 4];
        qfl[k16][0] = smw[WQL + rA*ST + cw];
        qfl[k16][1] = smw[WQL + (rA+8)*ST + cw];
        qfl[k16][2] = smw[WQL + rA*ST + cw + 4];
        qfl[k16][3] = smw[WQL + (rA+8)*ST + cw + 4];
    }

    float acc[8][4];
    #pragma unroll
    for (int nt = 0; nt < 8; nt++)
        #pragma unroll
        for (int i = 0; i < 4; i++) acc[nt][i] = 0.f;

    const float ZOFF = -THRESH * SHARP;

    for (int it = 0; it < TLEN/64; it++) {
        CP_WAIT0();
        __syncthreads();

        if (it + 1 < TLEN/64) {
            size_t s0n = (size_t)(it + 1)*64;
            uint32_t kvb = smbase + (KV0 + ((it+1)&1)*KVSTAGE)*4;
            size_t koff = s0n*HD*2;
            cp16(kvb + soff0, khg + koff + (size_t)e0*16);
            cp16(kvb + soff1, khg + koff + (size_t)e1*16);
            cp16(kvb + 64*ST*4 + soff0, klg + koff + (size_t)e0*16);
            cp16(kvb + 64*ST*4 + soff1, klg + koff + (size_t)e1*16);
            size_t vcoff = s0n*2;
            cp16(kvb + 2*64*ST*4 + soff0, vhg + vcoff + voff0);
            cp16(kvb + 2*64*ST*4 + soff1, vhg + vcoff + voff1);
            cp16(kvb + 3*64*ST*4 + soff0, vlg + vcoff + voff0);
            cp16(kvb + 3*64*ST*4 + soff1, vlg + vcoff + voff1);
            CP_COMMIT();
        }

        int kvw = KV0 + (it & 1)*KVSTAGE;
        uint32_t KHb = smbase + kvw*4;
        uint32_t KLb = KHb + 64*ST*4;
        uint32_t VHb = KHb + 2*64*ST*4;
        uint32_t VLb = KHb + 3*64*ST*4;

        float c[8][4];
        #pragma unroll
        for (int nt = 0; nt < 8; nt++)
            #pragma unroll
            for (int i = 0; i < 4; i++) c[nt][i] = 0.f;

        #pragma unroll
        for (int k16 = 0; k16 < 4; k16++) {
            #pragma unroll
            for (int ntp = 0; ntp < 4; ntp++) {
                uint32_t aoff = ((ntp*16 + rowsel)*ST + k16*8 + colsel)*4;
                uint32_t bh[4], bl[4];
                ldsm4(bh, KHb + aoff);
                ldsm4(bl, KLb + aoff);
                mma_bf16(c[2*ntp],   qfh[k16], bh);
                mma_bf16(c[2*ntp],   qfh[k16], bl);
                mma_bf16(c[2*ntp],   qfl[k16], bh);
                mma_bf16(c[2*ntp+1], qfh[k16], bh + 2);
                mma_bf16(c[2*ntp+1], qfh[k16], bl + 2);
                mma_bf16(c[2*ntp+1], qfl[k16], bh + 2);
            }
        }

        uint32_t ph[8][2], pl[8][2];
        #pragma unroll
        for (int nt = 0; nt < 8; nt++)
            #pragma unroll
            for (int half = 0; half < 2; half++) {
                float z0 = fmaf(c[nt][half*2],   SHARP, ZOFF);
                float z1 = fmaf(c[nt][half*2+1], SHARP, ZOFF);
                float p0 = __fdividef(1.0f, 1.0f + __expf(-z0));
                float p1 = __fdividef(1.0f, 1.0f + __expf(-z1));
                ph[nt][half] = bfpack2(p0, p1);
                pl[nt][half] = bfpack2(bflo(p0), bflo(p1));
            }

        #pragma unroll
        for (int k16 = 0; k16 < 4; k16++) {
            uint32_t ah[4] = { ph[2*k16][0], ph[2*k16][1], ph[2*k16+1][0], ph[2*k16+1][1] };
            uint32_t al[4] = { pl[2*k16][0], pl[2*k16][1], pl[2*k16+1][0], pl[2*k16+1][1] };
            #pragma unroll
            for (int ntp = 0; ntp < 4; ntp++) {
                uint32_t aoff = ((ntp*16 + rowsel)*ST + k16*8 + colsel)*4;
                uint32_t bh[4], bl[4];
                ldsm4(bh, VHb + aoff);
                ldsm4(bl, VLb + aoff);
                mma_bf16(acc[2*ntp],   ah, bh);
                mma_bf16(acc[2*ntp],   ah, bl);
                mma_bf16(acc[2*ntp],   al, bh);
                mma_bf16(acc[2*ntp+1], ah, bh + 2);
                mma_bf16(acc[2*ntp+1], ah, bl + 2);
                mma_bf16(acc[2*ntp+1], al, bh + 2);
            }
        }
    }

    size_t cb = ((size_t)(b*TLEN) + t0)*DIM + h*HD;
    #pragma unroll
    for (int nt = 0; nt < 8; nt++)
        #pragma unroll
        for (int half = 0; half < 2; half++) {
            int row = warp*16 + (lane >> 2) + half*8;
            int col = nt*8 + (lane & 3)*2;
            float g2 = gqs[row];
            float v0 = acc[nt][half*2]*g2, v1 = acc[nt][half*2+1]*g2;
            size_t off = cb + (size_t)row*DIM + col;
            *(uint32_t*)&d_Ch[off] = bfpack2(v0, v1);
            *(uint32_t*)&d_Cl[off] = bfpack2(bflo(v0), bflo(v1));
        }
}

// ---------------- launch ------------------------------------------------------
extern "C" void kernel_launch(void* const* d_in, const int* in_sizes, int n_in,
                              void* d_out, int out_size) {
    const float* x   = (const float*)d_in[0];
    const float* Wq  = (const float*)d_in[1];
    const float* Wk  = (const float*)d_in[2];
    const float* Wv  = (const float*)d_in[3];
    const float* gqv = (const float*)d_in[4];
    const float* gkv = (const float*)d_in[5];
    const float* Wo  = (const float*)d_in[6];
    const float* bo  = (const float*)d_in[7];
    const float* lnw = (const float*)d_in[8];
    const float* lnb = (const float*)d_in[9];
    float* out = (float*)d_out;

    cudaFuncSetAttribute(attn_tc, cudaFuncAttributeMaxDynamicSharedMemorySize, ATT_SMEM);
    cudaFuncSetAttribute(gemm_ts<0>, cudaFuncAttributeMaxDynamicSharedMemorySize, GEMM_SMEM);
    cudaFuncSetAttribute(gemm_ts<1>, cudaFuncAttributeMaxDynamicSharedMemorySize, GEMM_SMEM);

    ln_kernel<<<ROWS, 256>>>(x, lnw, lnb);
    split_x<<<ROWS*DIM/1024, 256>>>(x);
    wsplit<<<dim3(32, 32, 4), dim3(32, 8)>>>(Wq, Wk, Wv, Wo);
    gemm_ts<0><<<dim3(8, 32, 3), 256, GEMM_SMEM>>>(nullptr, nullptr);
    normgate_kernel<<<HROWS*32/256, 256>>>(gqv, gkv);
    attn_tc<<<dim3(TLEN/128, HEADS, BATCH), 256, ATT_SMEM>>>();
    gemm_ts<1><<<dim3(8, 32), 256, GEMM_SMEM>>>(bo, out);
}